// round 14
// baseline (speedup 1.0000x reference)
#include <cuda_runtime.h>
#include <cuda_bf16.h>
#include <cstdint>

#define N_NODES 50000
#define N_EDGES 800000
#define F_IN    64
#define F_MID   128
#define GTILE   64           // rows per fused-GEMM tile (2 CTAs/SM)
#define NTILES  ((N_NODES + GTILE - 1) / GTILE)   // 782

typedef unsigned long long u64;

// ---------------- scratch (device globals; no allocations) ----------------
__device__ int   g_deg_out[N_NODES];
__device__ int   g_deg_in [N_NODES];
__device__ float g_norm_src[N_NODES];
__device__ float g_norm_dst[N_NODES];
__device__ int   g_off [N_NODES];
__device__ int   g_alloc;
__device__ int   g_rank[N_EDGES];
__device__ int   g_esrc[N_EDGES];
__device__ float g_hs  [(size_t)N_NODES * F_IN];
__device__ float g_agg1[(size_t)N_NODES * F_IN];
__device__ float g_t2  [(size_t)N_NODES * F_IN];

// Dynamic smem layout for fused GEMM (float offsets), 2-CTA/SM budget.
#define WS1_OFF 0                              // [64*128]        8192 floats
#define WS2_OFF 8192                           // [128*64]        8192 floats
#define AS_OFF  16384                          // [64 rows][64 k] 4096 floats
#define H1_OFF  20480                          // [64 rows][128]  8192 floats
#define SMEM_FLOATS (H1_OFF + GTILE * 128)     // 28672
#define SMEM_BYTES (SMEM_FLOATS * 4)           // 114688

// ---------------- f32x2 helpers (bit-exact vs scalar fp32) ----------------
__device__ __forceinline__ u64 pack_dup(float v) {
    u64 r; asm("mov.b64 %0, {%1,%1};" : "=l"(r) : "f"(v)); return r;
}
__device__ __forceinline__ void fma2(u64& d, u64 a, u64 b) {
    asm("fma.rn.f32x2 %0, %1, %2, %0;" : "+l"(d) : "l"(a), "l"(b));
}
__device__ __forceinline__ float2 unpack2(u64 v) {
    float2 r; asm("mov.b64 {%0,%1}, %2;" : "=f"(r.x), "=f"(r.y) : "l"(v)); return r;
}

// ---------------- kernels ----------------

__global__ void zero_kernel() {
    int i = blockIdx.x * blockDim.x + threadIdx.x;
    if (i < N_NODES) { g_deg_out[i] = 0; g_deg_in[i] = 0; }
    if (i == 0) g_alloc = 0;
}

__global__ void degree_kernel(const int* __restrict__ src,
                              const int* __restrict__ dst) {
    int t = blockIdx.x * blockDim.x + threadIdx.x;
    if (t >= N_EDGES / 2) return;
    int2 s = __ldg(reinterpret_cast<const int2*>(src) + t);
    int2 d = __ldg(reinterpret_cast<const int2*>(dst) + t);
    atomicAdd(&g_deg_out[s.x], 1);
    atomicAdd(&g_deg_out[s.y], 1);
    int2 r;
    r.x = atomicAdd(&g_deg_in[d.x], 1);
    r.y = atomicAdd(&g_deg_in[d.y], 1);
    reinterpret_cast<int2*>(g_rank)[t] = r;
}

// Scan for CSR offsets + norms + fused prescale of this block's 256 rows.
__global__ __launch_bounds__(256) void norm_offset_prescale_kernel(const float* __restrict__ h) {
    __shared__ int   s[256];
    __shared__ int   base;
    __shared__ float ns_s[256];
    int t = threadIdx.x;
    int i = blockIdx.x * 256 + t;
    int deg = 0, dout = 0;
    if (i < N_NODES) { deg = g_deg_in[i]; dout = g_deg_out[i]; }
    s[t] = deg;
    __syncthreads();
#pragma unroll
    for (int o = 1; o < 256; o <<= 1) {
        int v = (t >= o) ? s[t - o] : 0;
        __syncthreads();
        s[t] += v;
        __syncthreads();
    }
    if (t == 255) base = atomicAdd(&g_alloc, s[255]);
    float nsv = rsqrtf(fmaxf((float)dout, 1.f));
    ns_s[t] = nsv;
    __syncthreads();
    if (i < N_NODES) {
        g_off[i] = base + s[t] - deg;
        g_norm_src[i] = nsv;
        g_norm_dst[i] = rsqrtf(fmaxf((float)deg, 1.f));
    }
    int base_row = blockIdx.x * 256;
    const float4* h4 = reinterpret_cast<const float4*>(h);
    float4* hs4 = reinterpret_cast<float4*>(g_hs);
#pragma unroll
    for (int j = 0; j < 16; j++) {
        int idx = j * 256 + t;
        int lr = idx >> 4;
        int c4 = idx & 15;
        int row = base_row + lr;
        if (row < N_NODES) {
            float ns = ns_s[lr];
            float4 v = __ldg(&h4[(size_t)row * 16 + c4]);
            v.x *= ns; v.y *= ns; v.z *= ns; v.w *= ns;
            hs4[(size_t)row * 16 + c4] = v;
        }
    }
}

__global__ void fill_kernel(const int* __restrict__ src,
                            const int* __restrict__ dst) {
    int t = blockIdx.x * blockDim.x + threadIdx.x;
    if (t >= N_EDGES / 2) return;
    int2 s = __ldg(reinterpret_cast<const int2*>(src) + t);
    int2 d = __ldg(reinterpret_cast<const int2*>(dst) + t);
    int2 r = *(reinterpret_cast<const int2*>(g_rank) + t);
    int px = __ldg(&g_off[d.x]) + r.x;
    int py = __ldg(&g_off[d.y]) + r.y;
    g_esrc[px] = s.x;
    g_esrc[py] = s.y;
}

__device__ __forceinline__ void acc_row(const float4* __restrict__ base4, int s, int c2,
                                        float4& a0, float4& a1) {
    const float4* p = base4 + (size_t)s * 16 + c2;
    float4 v0 = __ldg(p), v1 = __ldg(p + 1);
    a0.x += v0.x; a0.y += v0.y; a0.z += v0.z; a0.w += v0.w;
    a1.x += v1.x; a1.y += v1.y; a1.z += v1.z; a1.w += v1.w;
}

__global__ void aggregate1_kernel() {
    int tid = blockIdx.x * blockDim.x + threadIdx.x;
    int n = tid >> 3;
    if (n >= N_NODES) return;
    int c2 = (tid & 7) << 1;
    int i   = __ldg(&g_off[n]);
    int end = i + __ldg(&g_deg_in[n]);
    const float4* hs4 = reinterpret_cast<const float4*>(g_hs);
    float4 a0 = make_float4(0.f,0.f,0.f,0.f);
    float4 a1 = a0;
    while ((i & 3) && i < end) acc_row(hs4, __ldg(&g_esrc[i++]), c2, a0, a1);
    const int4* e4 = reinterpret_cast<const int4*>(g_esrc);
    for (; i + 4 <= end; i += 4) {
        int4 q = __ldg(&e4[i >> 2]);
        acc_row(hs4, q.x, c2, a0, a1);
        acc_row(hs4, q.y, c2, a0, a1);
        acc_row(hs4, q.z, c2, a0, a1);
        acc_row(hs4, q.w, c2, a0, a1);
    }
    for (; i < end; i++) acc_row(hs4, __ldg(&g_esrc[i]), c2, a0, a1);
    float4* o = reinterpret_cast<float4*>(g_agg1) + (size_t)n * 16 + c2;
    o[0] = a0; o[1] = a1;
}

// Fused persistent GEMM, 512 threads, grid=296 (2 CTAs/SM), 64-row tiles.
__global__ __launch_bounds__(512) void fused_gemm_kernel(const float* __restrict__ W1,
                                                         const float* __restrict__ b1,
                                                         const float* __restrict__ W2) {
    extern __shared__ __align__(16) float sm[];
    float* Ws1 = sm + WS1_OFF;    // [k][128 cols]
    float* Ws2 = sm + WS2_OFF;    // [k][64 cols]
    float* As  = sm + AS_OFF;     // [row 64][k 64] row-major
    float* H1s = sm + H1_OFF;     // [row 64][col 128] row-major
    int t = threadIdx.x;

    for (int i = t; i < F_IN * F_MID / 4; i += 512)
        reinterpret_cast<float4*>(Ws1)[i] = __ldg(reinterpret_cast<const float4*>(W1) + i);
    for (int i = t; i < F_MID * F_IN / 4; i += 512)
        reinterpret_cast<float4*>(Ws2)[i] = __ldg(reinterpret_cast<const float4*>(W2) + i);

    int ct = t & 31;       // phase1 cols 4*ct (of 128)
    int rt = t >> 5;       // phase1 rows 4*rt (of 64), 0..15
    int ct2 = t & 15;      // phase2 cols 4*ct2 (of 64)
    int rt2 = t >> 4;      // phase2 rows 2*rt2 (of 64), 0..31

    float4 bb = __ldg(reinterpret_cast<const float4*>(b1) + ct);

    for (int tile = blockIdx.x; tile < NTILES; tile += gridDim.x) {
        int row0 = tile * GTILE;
        __syncthreads();   // previous tile's phase2 reads complete

        for (int i = t; i < GTILE * F_IN / 4; i += 512) {
            int r  = i >> 4;
            int c4 = i & 15;
            int row = row0 + r;
            float4 v = (row < N_NODES)
                ? *reinterpret_cast<const float4*>(g_agg1 + (size_t)row * F_IN + (c4 << 2))
                : make_float4(0.f, 0.f, 0.f, 0.f);
            *reinterpret_cast<float4*>(&As[r * F_IN + (c4 << 2)]) = v;
        }
        __syncthreads();

        // ---- phase 1: 4 rows x 4 cols (2 col-pairs) per thread, FFMA2 ----
        u64 acc[4][2];
#pragma unroll
        for (int j = 0; j < 4; j++) { acc[j][0] = 0ull; acc[j][1] = 0ull; }

        int rbase = rt << 2;
#pragma unroll 4
        for (int k4 = 0; k4 < F_IN / 4; k4++) {
            float4 a0 = *reinterpret_cast<const float4*>(&As[(rbase + 0) * F_IN + (k4 << 2)]);
            float4 a1 = *reinterpret_cast<const float4*>(&As[(rbase + 1) * F_IN + (k4 << 2)]);
            float4 a2 = *reinterpret_cast<const float4*>(&As[(rbase + 2) * F_IN + (k4 << 2)]);
            float4 a3 = *reinterpret_cast<const float4*>(&As[(rbase + 3) * F_IN + (k4 << 2)]);
#pragma unroll
            for (int kk = 0; kk < 4; kk++) {
                ulonglong2 w = *reinterpret_cast<const ulonglong2*>(
                    &Ws1[((k4 << 2) + kk) * F_MID + (ct << 2)]);
                float av0 = kk == 0 ? a0.x : kk == 1 ? a0.y : kk == 2 ? a0.z : a0.w;
                float av1 = kk == 0 ? a1.x : kk == 1 ? a1.y : kk == 2 ? a1.z : a1.w;
                float av2 = kk == 0 ? a2.x : kk == 1 ? a2.y : kk == 2 ? a2.z : a2.w;
                float av3 = kk == 0 ? a3.x : kk == 1 ? a3.y : kk == 2 ? a3.z : a3.w;
                u64 p0 = pack_dup(av0), p1 = pack_dup(av1);
                u64 p2 = pack_dup(av2), p3 = pack_dup(av3);
                fma2(acc[0][0], p0, w.x); fma2(acc[0][1], p0, w.y);
                fma2(acc[1][0], p1, w.x); fma2(acc[1][1], p1, w.y);
                fma2(acc[2][0], p2, w.x); fma2(acc[2][1], p2, w.y);
                fma2(acc[3][0], p3, w.x); fma2(acc[3][1], p3, w.y);
            }
        }
#pragma unroll
        for (int j = 0; j < 4; j++) {
            int lr = rbase + j;
            int row = row0 + lr;
            float nd = (row < N_NODES) ? __ldg(&g_norm_dst[row]) : 0.f;
            float2 u0 = unpack2(acc[j][0]);
            float2 u1 = unpack2(acc[j][1]);
            float4 o;
            o.x = fmaxf(fmaf(u0.x, nd, bb.x), 0.f);
            o.y = fmaxf(fmaf(u0.y, nd, bb.y), 0.f);
            o.z = fmaxf(fmaf(u1.x, nd, bb.z), 0.f);
            o.w = fmaxf(fmaf(u1.y, nd, bb.w), 0.f);
            *reinterpret_cast<float4*>(&H1s[lr * 128 + (ct << 2)]) = o;
        }
        __syncthreads();

        // ---- phase 2: 2 rows x 4 cols (2 col-pairs) per thread, FFMA2 ----
        u64 acc2[2][2];
        acc2[0][0] = acc2[0][1] = acc2[1][0] = acc2[1][1] = 0ull;

        int r0 = rt2 << 1;
#pragma unroll 4
        for (int k4 = 0; k4 < F_MID / 4; k4++) {
            float4 a0v = *reinterpret_cast<const float4*>(&H1s[r0 * 128 + (k4 << 2)]);
            float4 a1v = *reinterpret_cast<const float4*>(&H1s[(r0 + 1) * 128 + (k4 << 2)]);
#pragma unroll
            for (int kk = 0; kk < 4; kk++) {
                ulonglong2 w = *reinterpret_cast<const ulonglong2*>(
                    &Ws2[((k4 << 2) + kk) * F_IN + (ct2 << 2)]);
                float av0 = kk == 0 ? a0v.x : kk == 1 ? a0v.y : kk == 2 ? a0v.z : a0v.w;
                float av1 = kk == 0 ? a1v.x : kk == 1 ? a1v.y : kk == 2 ? a1v.z : a1v.w;
                u64 p0 = pack_dup(av0), p1 = pack_dup(av1);
                fma2(acc2[0][0], p0, w.x); fma2(acc2[0][1], p0, w.y);
                fma2(acc2[1][0], p1, w.x); fma2(acc2[1][1], p1, w.y);
            }
        }
#pragma unroll
        for (int j = 0; j < 2; j++) {
            int row = row0 + r0 + j;
            if (row < N_NODES) {
                float ns = __ldg(&g_norm_src[row]);
                float2 u0 = unpack2(acc2[j][0]);
                float2 u1 = unpack2(acc2[j][1]);
                float4 o;
                o.x = u0.x * ns; o.y = u0.y * ns;
                o.z = u1.x * ns; o.w = u1.y * ns;
                *reinterpret_cast<float4*>(g_t2 + (size_t)row * F_IN + (ct2 << 2)) = o;
            }
        }
    }
}

__global__ void aggregate2_kernel(const float* __restrict__ b2,
                                  float* __restrict__ out) {
    int tid = blockIdx.x * blockDim.x + threadIdx.x;
    int n = tid >> 3;
    if (n >= N_NODES) return;
    int c2 = (tid & 7) << 1;
    int i   = __ldg(&g_off[n]);
    int end = i + __ldg(&g_deg_in[n]);
    const float4* t4 = reinterpret_cast<const float4*>(g_t2);
    float4 a0 = make_float4(0.f,0.f,0.f,0.f);
    float4 a1 = a0;
    while ((i & 3) && i < end) acc_row(t4, __ldg(&g_esrc[i++]), c2, a0, a1);
    const int4* e4 = reinterpret_cast<const int4*>(g_esrc);
    for (; i + 4 <= end; i += 4) {
        int4 q = __ldg(&e4[i >> 2]);
        acc_row(t4, q.x, c2, a0, a1);
        acc_row(t4, q.y, c2, a0, a1);
        acc_row(t4, q.z, c2, a0, a1);
        acc_row(t4, q.w, c2, a0, a1);
    }
    for (; i < end; i++) acc_row(t4, __ldg(&g_esrc[i]), c2, a0, a1);

    float nd = g_norm_dst[n];
    float4 b0 = reinterpret_cast<const float4*>(b2)[c2];
    float4 b1v = reinterpret_cast<const float4*>(b2)[c2 + 1];
    float4 o0, o1;
    o0.x = fmaf(a0.x, nd, b0.x);  o0.y = fmaf(a0.y, nd, b0.y);
    o0.z = fmaf(a0.z, nd, b0.z);  o0.w = fmaf(a0.w, nd, b0.w);
    o1.x = fmaf(a1.x, nd, b1v.x); o1.y = fmaf(a1.y, nd, b1v.y);
    o1.z = fmaf(a1.z, nd, b1v.z); o1.w = fmaf(a1.w, nd, b1v.w);
    float4* o = reinterpret_cast<float4*>(out) + (size_t)n * 16 + c2;
    o[0] = o0; o[1] = o1;
}

// ---------------- launch ----------------
extern "C" void kernel_launch(void* const* d_in, const int* in_sizes, int n_in,
                              void* d_out, int out_size) {
    const float* h   = (const float*)d_in[0];
    const int*   src = (const int*)  d_in[1];
    const int*   dst = (const int*)  d_in[2];
    const float* W1  = (const float*)d_in[3];
    const float* b1  = (const float*)d_in[4];
    const float* W2  = (const float*)d_in[5];
    const float* b2  = (const float*)d_in[6];
    float* out = (float*)d_out;

    cudaFuncSetAttribute(fused_gemm_kernel,
                         cudaFuncAttributeMaxDynamicSharedMemorySize, SMEM_BYTES);

    zero_kernel<<<(N_NODES + 255) / 256, 256>>>();
    degree_kernel<<<(N_EDGES / 2 + 255) / 256, 256>>>(src, dst);
    norm_offset_prescale_kernel<<<(N_NODES + 255) / 256, 256>>>(h);
    fill_kernel<<<(N_EDGES / 2 + 255) / 256, 256>>>(src, dst);

    const int a_threads = N_NODES * 8;
    aggregate1_kernel<<<(a_threads + 255) / 256, 256>>>();

    fused_gemm_kernel<<<296, 512, SMEM_BYTES>>>(W1, b1, W2);

    aggregate2_kernel<<<(a_threads + 255) / 256, 256>>>(b2, out);
}